// round 5
// baseline (speedup 1.0000x reference)
#include <cuda_runtime.h>
#include <cuda_bf16.h>
#include <math.h>

// Problem constants (fixed by the dataset): B=128, S=1024, d=64, D=64.
#define S_LEN   1024
#define D_DIM   64
#define NSYM    64
#define DEPTH   4      // ring depth; MUST divide S_LEN (1024 % DEPTH == 0)
#define HSTRIDE 80     // floats between p0/p1 partial arrays (16-bank skew)

// Transposed bf16 core: coreT[s][j][i] = bf16(core[s][i][j]).  512 KB static.
__device__ __nv_bfloat16 g_coreT[NSYM * D_DIM * D_DIM];

__global__ void ttrain_prep_kernel(const float* __restrict__ core) {
    int idx = blockIdx.x * blockDim.x + threadIdx.x;
    if (idx < NSYM * D_DIM * D_DIM) {
        int s   = idx >> 12;
        int rem = idx & 4095;
        int i   = rem >> 6;
        int j   = rem & 63;
        g_coreT[(s << 12) + (j << 6) + i] = __float2bfloat16(core[idx]);
    }
}

__device__ __forceinline__ unsigned long long fadd2(unsigned long long a,
                                                    unsigned long long b) {
    unsigned long long d;
    asm("add.rn.f32x2 %0, %1, %2;" : "=l"(d) : "l"(a), "l"(b));
    return d;
}
__device__ __forceinline__ unsigned long long ffma2(unsigned long long a,
                                                    unsigned long long b,
                                                    unsigned long long c) {
    unsigned long long d;
    asm("fma.rn.f32x2 %0, %1, %2, %3;" : "=l"(d) : "l"(a), "l"(b), "l"(c));
    return d;
}
// bf16 pair (packed u32) -> packed f32x2 {lo=bf0, hi=bf1}
__device__ __forceinline__ unsigned long long bf2f2(unsigned int w) {
    unsigned long long d;
    asm("mov.b64 %0, {%1, %2};" : "=l"(d)
        : "r"(w << 16), "r"(w & 0xffff0000u));
    return d;
}

// Two independent batch chains per CTA (8 warps): warps 0-3 = chain 0,
// warps 4-7 = chain 1; chain warps land pairwise on the same 4 SMSPs so each
// chain's stall cycles (BAR / LDS / LDG scoreboard) are filled by the other
// chain's issue. Chains sync only their own 128 threads via named barriers.
// Within a chain: warp w owns j in [16w,16w+16); lane l: j=16w+(l>>1), p=l&1.
// Thread (j,p) accumulates i in [32p,32p+32); both partials go to smem and
// the consumer combines them next step (f32x2 adds; no shfl on the path).
// Renorm: every step, exact power-of-two scale from exponent of c[0]
// (uniform; cancels exactly in the final log formula).
__global__ __launch_bounds__(256, 1) void ttrain_main_kernel(
    const int*   __restrict__ X,
    const float* __restrict__ lb,
    const float* __restrict__ rb,
    float*       __restrict__ out)
{
    __shared__ __align__(16) float s_p[2][2][2][HSTRIDE]; // [chain][buf][half][]
    __shared__ float s_red[2][4];
    __shared__ int   sX[2][S_LEN];

    const int tid   = threadIdx.x;
    const int chain = tid >> 7;          // 0 or 1
    const int ct    = tid & 127;         // thread id within chain
    const int b     = (blockIdx.x << 1) + chain;
    const int w     = ct >> 5;
    const int l     = ct & 31;
    const int j     = (w << 4) + (l >> 1);
    const int p     = l & 1;

    const int* Xb = X + b * S_LEN;
    for (int k = ct; k < S_LEN; k += 128) sX[chain][k] = Xb[k];
    if (ct < D_DIM) {                    // initial c = left_boundary
        int o = ct + ((ct >> 5) << 2);   // pad: +4 floats per 32
        s_p[chain][0][0][o] = lb[ct];
        s_p[chain][0][1][o] = 0.f;
    }
    __syncthreads();

#define CHAIN_BAR() asm volatile("bar.sync %0, 128;" :: "r"(chain + 1) : "memory")

    // Per-thread bf16 weight slice: coreT[s] + j*64 + p*32 bf16 = 64 bytes.
    const uint4* wbase = reinterpret_cast<const uint4*>(g_coreT);
    const int    toff  = (j << 3) + (p << 2);    // in uint4 units

    uint4 ring[DEPTH][4];
#define LOADW(dst, tt) {                                                       \
        const uint4* pw_ =                                                     \
            wbase + (sX[chain][(tt) & (S_LEN - 1)] << 9) + toff;               \
        (dst)[0] = pw_[0]; (dst)[1] = pw_[1];                                  \
        (dst)[2] = pw_[2]; (dst)[3] = pw_[3]; }

    LOADW(ring[0], 0)
    LOADW(ring[1], 1)
    LOADW(ring[2], 2)

    const int ibase = p ? 36 : 0;          // padded float offset of my i-half
    const int jo    = j + ((j >> 5) << 2); // padded output offset

    int e_total = 0;

    for (int t0 = 0; t0 < S_LEN; t0 += DEPTH) {     // 1024 % DEPTH == 0
#pragma unroll
        for (int u = 0; u < DEPTH; ++u) {
            const int t = t0 + u;
            LOADW(ring[(u + DEPTH - 1) % DEPTH], t + DEPTH - 1)

            const int    buf = t & 1;
            const float* P0  = s_p[chain][buf][0];
            const float* P1  = s_p[chain][buf][1];

            // Uniform power-of-two renorm scale from c[0] (exact; cancels).
            float c0 = P0[0] + P1[0];
            int   e  = ((__float_as_int(c0) >> 23) & 0xff) - 127;
            e = e < -126 ? -126 : (e > 126 ? 126 : e);
            e_total += e;
            const float scale = __int_as_float((127 - e) << 23);

            const ulonglong2* Av = reinterpret_cast<const ulonglong2*>(P0 + ibase);
            const ulonglong2* Bv = reinterpret_cast<const ulonglong2*>(P1 + ibase);
            const unsigned int* wd =
                reinterpret_cast<const unsigned int*>(ring[u]);

            unsigned long long acc0 = 0ull, acc1 = 0ull;
#pragma unroll
            for (int q = 0; q < 8; ++q) {
                ulonglong2 av = Av[q], bv = Bv[q];
                unsigned long long cA = fadd2(av.x, bv.x); // {c[4q],c[4q+1]}
                unsigned long long cB = fadd2(av.y, bv.y); // {c[4q+2],c[4q+3]}
                acc0 = ffma2(cA, bf2f2(wd[2 * q]),     acc0);
                acc1 = ffma2(cB, bf2f2(wd[2 * q + 1]), acc1);
            }
            float2 f0 = *reinterpret_cast<float2*>(&acc0);
            float2 f1 = *reinterpret_cast<float2*>(&acc1);
            float  tot = ((f0.x + f0.y) + (f1.x + f1.y)) * scale;

            s_p[chain][buf ^ 1][p][jo] = tot;   // my partial; no shfl
            CHAIN_BAR();
        }
    }
#undef LOADW

    // Final contraction with right boundary + log-likelihood (per chain).
    float v = 0.f;
    if (ct < D_DIM) {
        int o = ct + ((ct >> 5) << 2);
        v = (s_p[chain][0][0][o] + s_p[chain][0][1][o]) * rb[ct];
    }
#pragma unroll
    for (int o = 16; o >= 1; o >>= 1)
        v += __shfl_xor_sync(0xffffffffu, v, o);
    if (l == 0) s_red[chain][w] = v;
    CHAIN_BAR();
    if (ct == 0) {
        double ov = (double)s_red[chain][0] + (double)s_red[chain][1] +
                    (double)s_red[chain][2] + (double)s_red[chain][3];
        out[b] = (float)(2.0 * ((double)e_total * 0.6931471805599453 +
                                log(fabs(ov))));
    }
#undef CHAIN_BAR
}

extern "C" void kernel_launch(void* const* d_in, const int* in_sizes, int n_in,
                              void* d_out, int out_size) {
    // metadata order: X [128*1024] i32, core [64*64*64] f32,
    //                 left_boundary [64] f32, right_boundary [64] f32
    const int*   X    = (const int*)  d_in[0];
    const float* core = (const float*)d_in[1];
    const float* lb   = (const float*)d_in[2];
    const float* rb   = (const float*)d_in[3];
    float*       out  = (float*)d_out;

    ttrain_prep_kernel<<<(NSYM * D_DIM * D_DIM + 255) / 256, 256>>>(core);
    ttrain_main_kernel<<<64, 256>>>(X, lb, rb, out);
}

// round 6
// speedup vs baseline: 2.1792x; 2.1792x over previous
#include <cuda_runtime.h>
#include <cuda_bf16.h>
#include <math.h>

// Problem constants (fixed by the dataset): B=128, S=1024, d=64, D=64.
#define S_LEN   1024
#define NSTEP   512     // fused pair steps; DEPTH must divide NSTEP
#define D_DIM   64
#define NSYM    64
#define NPAIR   (NSYM * NSYM)
#define DEPTH   4       // ring depth; 512 % 4 == 0
#define HSTRIDE 80      // floats between p0/p1 partial arrays (16-bank skew)

// Pair table, transposed bf16: pairT[p][k][i] = bf16( sum_j core[s1][i][j]*core[s2][j][k] ),
// p = s1*64 + s2.  4096 * 64 * 64 * 2B = 32 MB (L2-resident).
__device__ __nv_bfloat16 g_pairT[NPAIR * D_DIM * D_DIM];

__device__ __forceinline__ unsigned long long fadd2(unsigned long long a,
                                                    unsigned long long b) {
    unsigned long long d;
    asm("add.rn.f32x2 %0, %1, %2;" : "=l"(d) : "l"(a), "l"(b));
    return d;
}
__device__ __forceinline__ unsigned long long ffma2(unsigned long long a,
                                                    unsigned long long b,
                                                    unsigned long long c) {
    unsigned long long d;
    asm("fma.rn.f32x2 %0, %1, %2, %3;" : "=l"(d) : "l"(a), "l"(b), "l"(c));
    return d;
}
__device__ __forceinline__ unsigned long long packdup(float x) {
    unsigned long long d;
    asm("mov.b64 %0, {%1, %1};" : "=l"(d) : "f"(x));
    return d;
}
// bf16 pair (packed u32, lo=element 2q) -> packed f32x2 {lo, hi}
__device__ __forceinline__ unsigned long long bf2f2(unsigned int w) {
    unsigned long long d;
    asm("mov.b64 %0, {%1, %2};" : "=l"(d)
        : "r"(w << 16), "r"(w & 0xffff0000u));
    return d;
}
// pack two f32 into one bf16x2 u32: low 16 = lo, high 16 = hi
__device__ __forceinline__ unsigned int bfpack(float lo, float hi) {
    unsigned int r;
    asm("cvt.rn.satfinite.bf16x2.f32 %0, %1, %2;" : "=r"(r) : "f"(hi), "f"(lo));
    return r;
}

// ---------------------------------------------------------------------------
// Prep: build the 4096-pair product table.  One CTA per (s1,s2) pair.
// PT[p][k][i] = sum_j core[s1][i][j] * core[s2][j][k], fp32 accumulate,
// stored bf16.  Warp w owns i in [16w,16w+16); lane l owns k in {2l, 2l+1}.
// ---------------------------------------------------------------------------
__global__ __launch_bounds__(128) void ttrain_pair_kernel(
    const float* __restrict__ core)
{
    const int p  = blockIdx.x;
    const int s1 = p >> 6;
    const int s2 = p & 63;

    __shared__ float AT[D_DIM * D_DIM];   // AT[j][i] = core[s1][i][j]
    __shared__ float Bs[D_DIM * D_DIM];   // Bs[j][k] = core[s2][j][k]

    const int tid = threadIdx.x;
    const float4* A4 = reinterpret_cast<const float4*>(core + (s1 << 12));
    const float4* B4 = reinterpret_cast<const float4*>(core + (s2 << 12));
    float4* Bs4 = reinterpret_cast<float4*>(Bs);

#pragma unroll
    for (int v = tid; v < 1024; v += 128) Bs4[v] = B4[v];
#pragma unroll
    for (int v = tid; v < 1024; v += 128) {
        float4 a = A4[v];
        int i = v >> 4;
        int j = (v & 15) << 2;
        AT[ j      * 64 + i] = a.x;
        AT[(j + 1) * 64 + i] = a.y;
        AT[(j + 2) * 64 + i] = a.z;
        AT[(j + 3) * 64 + i] = a.w;
    }
    __syncthreads();

    const int w  = tid >> 5;
    const int l  = tid & 31;
    const int k0 = l << 1;       // this thread: k0, k0+1
    const int ib = w << 4;       // i in [ib, ib+16)

    unsigned long long acc0[8], acc1[8];   // f32x2 over i-pairs, per k
#pragma unroll
    for (int q = 0; q < 8; ++q) { acc0[q] = 0ull; acc1[q] = 0ull; }

#pragma unroll 8
    for (int j = 0; j < 64; ++j) {
        float2 b2 = *reinterpret_cast<const float2*>(Bs + j * 64 + k0);
        unsigned long long bd0 = packdup(b2.x);
        unsigned long long bd1 = packdup(b2.y);
        const ulonglong2* av =
            reinterpret_cast<const ulonglong2*>(AT + j * 64 + ib);
        ulonglong2 a01 = av[0], a23 = av[1], a45 = av[2], a67 = av[3];
        acc0[0] = ffma2(a01.x, bd0, acc0[0]);
        acc0[1] = ffma2(a01.y, bd0, acc0[1]);
        acc0[2] = ffma2(a23.x, bd0, acc0[2]);
        acc0[3] = ffma2(a23.y, bd0, acc0[3]);
        acc0[4] = ffma2(a45.x, bd0, acc0[4]);
        acc0[5] = ffma2(a45.y, bd0, acc0[5]);
        acc0[6] = ffma2(a67.x, bd0, acc0[6]);
        acc0[7] = ffma2(a67.y, bd0, acc0[7]);
        acc1[0] = ffma2(a01.x, bd1, acc1[0]);
        acc1[1] = ffma2(a01.y, bd1, acc1[1]);
        acc1[2] = ffma2(a23.x, bd1, acc1[2]);
        acc1[3] = ffma2(a23.y, bd1, acc1[3]);
        acc1[4] = ffma2(a45.x, bd1, acc1[4]);
        acc1[5] = ffma2(a45.y, bd1, acc1[5]);
        acc1[6] = ffma2(a67.x, bd1, acc1[6]);
        acc1[7] = ffma2(a67.y, bd1, acc1[7]);
    }

    // Pack to bf16 and store: u32 element index = p*2048 + k*32 + i/2.
    unsigned int* outw = reinterpret_cast<unsigned int*>(g_pairT);
    unsigned int r0[8], r1[8];
#pragma unroll
    for (int q = 0; q < 8; ++q) {
        float2 f0 = *reinterpret_cast<float2*>(&acc0[q]);
        float2 f1 = *reinterpret_cast<float2*>(&acc1[q]);
        r0[q] = bfpack(f0.x, f0.y);
        r1[q] = bfpack(f1.x, f1.y);
    }
    uint4* dst0 = reinterpret_cast<uint4*>(outw + (p << 11) + k0 * 32 + (ib >> 1));
    uint4* dst1 = reinterpret_cast<uint4*>(outw + (p << 11) + (k0 + 1) * 32 + (ib >> 1));
    dst0[0] = make_uint4(r0[0], r0[1], r0[2], r0[3]);
    dst0[1] = make_uint4(r0[4], r0[5], r0[6], r0[7]);
    dst1[0] = make_uint4(r1[0], r1[1], r1[2], r1[3]);
    dst1[1] = make_uint4(r1[4], r1[5], r1[6], r1[7]);
}

// ---------------------------------------------------------------------------
// Main chain: identical datapath to the proven 250us kernel, but 512 fused
// steps over the pair table.  One CTA (128 threads) per batch element.
// warp w owns outputs j in [16w,16w+16); lane l: j = 16w + (l>>1), p = l&1.
// Thread (j,p) accumulates i in [32p,32p+32); both partials stored to smem,
// combined by the consumer next step (f32x2 adds; no shfl on the path).
// Renorm each step: exact power-of-two scale from exponent of c[0] (cancels).
// ---------------------------------------------------------------------------
__global__ __launch_bounds__(128, 1) void ttrain_main_kernel(
    const int*   __restrict__ X,
    const float* __restrict__ lb,
    const float* __restrict__ rb,
    float*       __restrict__ out)
{
    __shared__ __align__(16) float s_p[2][2][HSTRIDE];  // [buf][i-half][]
    __shared__ float s_red[4];
    __shared__ int   sP[NSTEP];

    const int tid = threadIdx.x;
    const int b   = blockIdx.x;
    const int w   = tid >> 5;
    const int l   = tid & 31;
    const int j   = (w << 4) + (l >> 1);
    const int p   = l & 1;

    // Stage fused pair indices: pidx[t] = X[2t]*64 + X[2t+1].
    const int2* Xb2 = reinterpret_cast<const int2*>(X + b * S_LEN);
    for (int k = tid; k < NSTEP; k += 128) {
        int2 x2 = Xb2[k];
        sP[k] = (x2.x << 6) | x2.y;
    }
    if (tid < D_DIM) {                    // initial c = left_boundary
        int o = tid + ((tid >> 5) << 2);
        s_p[0][0][o] = lb[tid];
        s_p[0][1][o] = 0.f;
    }
    __syncthreads();

    // Per-thread bf16 weight slice: pairT[p] + j*64 + p*32 bf16 = 64 bytes.
    const uint4* wbase = reinterpret_cast<const uint4*>(g_pairT);
    const int    toff  = (j << 3) + (p << 2);     // uint4 units

    uint4 ring[DEPTH][4];
#define LOADW(dst, tt) {                                                   \
        const uint4* pw_ = wbase + (sP[(tt) & (NSTEP - 1)] << 9) + toff;   \
        (dst)[0] = pw_[0]; (dst)[1] = pw_[1];                              \
        (dst)[2] = pw_[2]; (dst)[3] = pw_[3]; }

    LOADW(ring[0], 0)
    LOADW(ring[1], 1)
    LOADW(ring[2], 2)

    const int ibase = p ? 36 : 0;          // padded float offset of my i-half
    const int jo    = j + ((j >> 5) << 2); // padded output offset

    int e_total = 0;

    for (int t0 = 0; t0 < NSTEP; t0 += DEPTH) {    // NSTEP % DEPTH == 0
#pragma unroll
        for (int u = 0; u < DEPTH; ++u) {
            const int t = t0 + u;
            LOADW(ring[(u + DEPTH - 1) % DEPTH], t + DEPTH - 1)

            const int    buf = t & 1;
            const float* P0  = s_p[buf][0];
            const float* P1  = s_p[buf][1];

            // Uniform power-of-two renorm scale from c[0] (exact; cancels).
            float c0 = P0[0] + P1[0];
            int   e  = ((__float_as_int(c0) >> 23) & 0xff) - 127;
            e = e < -126 ? -126 : (e > 126 ? 126 : e);
            e_total += e;
            const float scale = __int_as_float((127 - e) << 23);

            const ulonglong2* Av = reinterpret_cast<const ulonglong2*>(P0 + ibase);
            const ulonglong2* Bv = reinterpret_cast<const ulonglong2*>(P1 + ibase);
            const unsigned int* wd =
                reinterpret_cast<const unsigned int*>(ring[u]);

            unsigned long long acc0 = 0ull, acc1 = 0ull;
#pragma unroll
            for (int q = 0; q < 8; ++q) {
                ulonglong2 av = Av[q], bv = Bv[q];
                unsigned long long cA = fadd2(av.x, bv.x); // {c[4q],c[4q+1]}
                unsigned long long cB = fadd2(av.y, bv.y); // {c[4q+2],c[4q+3]}
                acc0 = ffma2(cA, bf2f2(wd[2 * q]),     acc0);
                acc1 = ffma2(cB, bf2f2(wd[2 * q + 1]), acc1);
            }
            float2 f0 = *reinterpret_cast<float2*>(&acc0);
            float2 f1 = *reinterpret_cast<float2*>(&acc1);
            float  tot = ((f0.x + f0.y) + (f1.x + f1.y)) * scale;

            s_p[buf ^ 1][p][jo] = tot;   // my partial; no shfl
            __syncthreads();
        }
    }
#undef LOADW

    // Final contraction with right boundary + log-likelihood.
    float v = 0.f;
    if (tid < D_DIM) {
        int o = tid + ((tid >> 5) << 2);
        v = (s_p[0][0][o] + s_p[0][1][o]) * rb[tid];
    }
#pragma unroll
    for (int o = 16; o >= 1; o >>= 1)
        v += __shfl_xor_sync(0xffffffffu, v, o);
    if (l == 0) s_red[w] = v;
    __syncthreads();
    if (tid == 0) {
        double ov = (double)s_red[0] + (double)s_red[1] +
                    (double)s_red[2] + (double)s_red[3];
        out[b] = (float)(2.0 * ((double)e_total * 0.6931471805599453 +
                                log(fabs(ov))));
    }
}

extern "C" void kernel_launch(void* const* d_in, const int* in_sizes, int n_in,
                              void* d_out, int out_size) {
    // metadata order: X [128*1024] i32, core [64*64*64] f32,
    //                 left_boundary [64] f32, right_boundary [64] f32
    const int*   X    = (const int*)  d_in[0];
    const float* core = (const float*)d_in[1];
    const float* lb   = (const float*)d_in[2];
    const float* rb   = (const float*)d_in[3];
    float*       out  = (float*)d_out;

    ttrain_pair_kernel<<<NPAIR, 128>>>(core);
    ttrain_main_kernel<<<128, 128>>>(X, lb, rb, out);
}

// round 8
// speedup vs baseline: 2.5334x; 1.1625x over previous
#include <cuda_runtime.h>
#include <cuda_bf16.h>
#include <math.h>

// Problem constants (fixed by the dataset): B=128, S=1024, d=64, D=64.
#define S_LEN   1024
#define NSTEP   512     // fused pair steps; DEPTH must divide NSTEP
#define D_DIM   64
#define NSYM    64
#define NPAIR   (NSYM * NSYM)
#define DEPTH   4       // ring depth; 512 % 4 == 0

// Pair table, transposed bf16: pairT[p][k][i] = bf16(sum_j core[s1][i][j]*core[s2][j][k]),
// p = s1*64 + s2, i consecutive (bf16x2 pairs match c packing).  32 MB, L2-resident.
__device__ __nv_bfloat16 g_pairT[NPAIR * D_DIM * D_DIM];

__device__ __forceinline__ unsigned long long ffma2(unsigned long long a,
                                                    unsigned long long b,
                                                    unsigned long long c) {
    unsigned long long d;
    asm("fma.rn.f32x2 %0, %1, %2, %3;" : "=l"(d) : "l"(a), "l"(b), "l"(c));
    return d;
}
__device__ __forceinline__ unsigned long long packdup(float x) {
    unsigned long long d;
    asm("mov.b64 %0, {%1, %1};" : "=l"(d) : "f"(x));
    return d;
}
// pack two f32 into one bf16x2 u32: low 16 = lo (even index), high 16 = hi
__device__ __forceinline__ unsigned int bfpack(float lo, float hi) {
    unsigned int r;
    asm("cvt.rn.satfinite.bf16x2.f32 %0, %1, %2;" : "=r"(r) : "f"(hi), "f"(lo));
    return r;
}
// reinterpret a u32 as bf16x2 (defined via union; no pointer aliasing games)
__device__ __forceinline__ __nv_bfloat162 u2bf2(unsigned int u) {
    union { unsigned int ui; __nv_bfloat162 b2; } cv;
    cv.ui = u;
    return cv.b2;
}

// ---------------------------------------------------------------------------
// Prep v2: build the 4096-pair table, FMA-bound (8i x 4k register tiling).
// One CTA (128 threads) per (s1,s2).  tid -> kb = tid&15 (k0=4*kb),
// ib = tid>>4 (i0=8*ib).  Per j: 2 LDS.128 (A) + 1 LDS.128 (B) + 16 FFMA2.
// ---------------------------------------------------------------------------
__global__ __launch_bounds__(128) void ttrain_pair_kernel(
    const float* __restrict__ core)
{
    const int p  = blockIdx.x;
    const int s1 = p >> 6;
    const int s2 = p & 63;

    __shared__ float AT[D_DIM * D_DIM];   // AT[j][i] = core[s1][i][j]
    __shared__ float Bs[D_DIM * D_DIM];   // Bs[j][k] = core[s2][j][k]

    const int tid = threadIdx.x;
    const float4* A4 = reinterpret_cast<const float4*>(core + (s1 << 12));
    const float4* B4 = reinterpret_cast<const float4*>(core + (s2 << 12));
    float4* Bs4 = reinterpret_cast<float4*>(Bs);

#pragma unroll
    for (int v = tid; v < 1024; v += 128) Bs4[v] = B4[v];
#pragma unroll
    for (int v = tid; v < 1024; v += 128) {
        float4 a = A4[v];
        int i = v >> 4;
        int jj = (v & 15) << 2;
        AT[ jj      * 64 + i] = a.x;
        AT[(jj + 1) * 64 + i] = a.y;
        AT[(jj + 2) * 64 + i] = a.z;
        AT[(jj + 3) * 64 + i] = a.w;
    }
    __syncthreads();

    const int kb = tid & 15;
    const int ib = tid >> 4;
    const int k0 = kb << 2;     // this thread: k0..k0+3
    const int i0 = ib << 3;     // this thread: i0..i0+7

    unsigned long long acc[4][4];   // [kk][i-pair], f32x2
#pragma unroll
    for (int a = 0; a < 4; ++a)
#pragma unroll
        for (int m = 0; m < 4; ++m) acc[a][m] = 0ull;

#pragma unroll 4
    for (int jj = 0; jj < 64; ++jj) {
        float4 b4 = *reinterpret_cast<const float4*>(Bs + jj * 64 + k0);
        unsigned long long bd0 = packdup(b4.x);
        unsigned long long bd1 = packdup(b4.y);
        unsigned long long bd2 = packdup(b4.z);
        unsigned long long bd3 = packdup(b4.w);
        const ulonglong2* av =
            reinterpret_cast<const ulonglong2*>(AT + jj * 64 + i0);
        ulonglong2 a01 = av[0], a23 = av[1];
        acc[0][0] = ffma2(a01.x, bd0, acc[0][0]);
        acc[0][1] = ffma2(a01.y, bd0, acc[0][1]);
        acc[0][2] = ffma2(a23.x, bd0, acc[0][2]);
        acc[0][3] = ffma2(a23.y, bd0, acc[0][3]);
        acc[1][0] = ffma2(a01.x, bd1, acc[1][0]);
        acc[1][1] = ffma2(a01.y, bd1, acc[1][1]);
        acc[1][2] = ffma2(a23.x, bd1, acc[1][2]);
        acc[1][3] = ffma2(a23.y, bd1, acc[1][3]);
        acc[2][0] = ffma2(a01.x, bd2, acc[2][0]);
        acc[2][1] = ffma2(a01.y, bd2, acc[2][1]);
        acc[2][2] = ffma2(a23.x, bd2, acc[2][2]);
        acc[2][3] = ffma2(a23.y, bd2, acc[2][3]);
        acc[3][0] = ffma2(a01.x, bd3, acc[3][0]);
        acc[3][1] = ffma2(a01.y, bd3, acc[3][1]);
        acc[3][2] = ffma2(a23.x, bd3, acc[3][2]);
        acc[3][3] = ffma2(a23.y, bd3, acc[3][3]);
    }

    // Store: element index (p,k,i) -> u32 index p*2048 + k*32 + i/2.
    unsigned int* outw = reinterpret_cast<unsigned int*>(g_pairT);
#pragma unroll
    for (int kk = 0; kk < 4; ++kk) {
        float2 f0 = *reinterpret_cast<float2*>(&acc[kk][0]);
        float2 f1 = *reinterpret_cast<float2*>(&acc[kk][1]);
        float2 f2 = *reinterpret_cast<float2*>(&acc[kk][2]);
        float2 f3 = *reinterpret_cast<float2*>(&acc[kk][3]);
        uint4 v = make_uint4(bfpack(f0.x, f0.y), bfpack(f1.x, f1.y),
                             bfpack(f2.x, f2.y), bfpack(f3.x, f3.y));
        *reinterpret_cast<uint4*>(
            outw + (p << 11) + ((k0 + kk) << 5) + (i0 >> 1)) = v;
    }
}

// ---------------------------------------------------------------------------
// Main chain, full-bf16 datapath.  One CTA (128 threads) per batch element,
// 512 fused steps.  warp w owns outputs j in [16w,16w+16); lane l:
// j = 16w + (l>>1), p = l&1.  Thread (j,p) does i in [32p,32p+32):
// 4 broadcast LDS.128 of bf16 c + 16 HFMA2.BF16 against the prefetched
// weight ring (already bf16x2 packed -> zero unpack), pair-combined via one
// shfl, then bf16 store.  Renorm each step: exact power-of-two scale from
// exponent of c[0] (uniform; cancels exactly in the final log formula);
// zero/denormal exponent field -> scale 1 (safety guard).
// ---------------------------------------------------------------------------
__global__ __launch_bounds__(128, 1) void ttrain_main_kernel(
    const int*   __restrict__ X,
    const float* __restrict__ lb,
    const float* __restrict__ rb,
    float*       __restrict__ out)
{
    __shared__ __align__(16) unsigned short s_c[2][D_DIM];  // bf16 c, dbl-buf
    __shared__ float s_red[4];
    __shared__ int   sP[NSTEP];

    const int tid = threadIdx.x;
    const int b   = blockIdx.x;
    const int w   = tid >> 5;
    const int l   = tid & 31;
    const int j   = (w << 4) + (l >> 1);
    const int p   = l & 1;

    // Stage fused pair indices: pidx[t] = X[2t]*64 + X[2t+1].
    const int2* Xb2 = reinterpret_cast<const int2*>(X + b * S_LEN);
    for (int k = tid; k < NSTEP; k += 128) {
        int2 x2 = Xb2[k];
        sP[k] = (x2.x << 6) | x2.y;
    }
    if (tid < D_DIM)
        s_c[0][tid] = __bfloat16_as_ushort(__float2bfloat16(lb[tid]));
    __syncthreads();

    // Per-thread weight slice: pairT[p] + j*64 + p*32 bf16 = 64 bytes.
    const uint4* wbase = reinterpret_cast<const uint4*>(g_pairT);
    const int    toff  = (j << 3) + (p << 2);     // uint4 units

    uint4 ring[DEPTH][4];
#define LOADW(dst, tt) {                                                   \
        const uint4* pw_ = wbase + (sP[(tt) & (NSTEP - 1)] << 9) + toff;   \
        (dst)[0] = pw_[0]; (dst)[1] = pw_[1];                              \
        (dst)[2] = pw_[2]; (dst)[3] = pw_[3]; }

    LOADW(ring[0], 0)
    LOADW(ring[1], 1)
    LOADW(ring[2], 2)

    int e_total = 0;

    for (int t0 = 0; t0 < NSTEP; t0 += DEPTH) {    // NSTEP % DEPTH == 0
#pragma unroll
        for (int u = 0; u < DEPTH; ++u) {
            const int t = t0 + u;
            LOADW(ring[(u + DEPTH - 1) % DEPTH], t + DEPTH - 1)

            const int buf = t & 1;

            // Renorm scale from c[0]'s exponent (bf16 shares fp32 exponent).
            // Guard: exponent field 0 (zero/denormal) -> no renorm this step.
            unsigned short c0b = s_c[buf][0];
            int ef = (c0b >> 7) & 0xff;
            int e  = (ef == 0) ? 0 : ef - 127;
            e = e < -96 ? -96 : (e > 96 ? 96 : e);
            e_total += e;
            const float scale = __int_as_float((127 - e) << 23);

            // My 32 c values (bf16): 64 bytes = 4 broadcast LDS.128 into a
            // true array (contiguous, register-resident under const index).
            const uint4* cv4 =
                reinterpret_cast<const uint4*>(&s_c[buf][p << 5]);
            uint4 carr[4];
#pragma unroll
            for (int m = 0; m < 4; ++m) carr[m] = cv4[m];

            const uint4* wq = ring[u];   // true array: 4 contiguous uint4

            __nv_bfloat162 a0 = __float2bfloat162_rn(0.f);
            __nv_bfloat162 a1 = __float2bfloat162_rn(0.f);
            __nv_bfloat162 a2 = __float2bfloat162_rn(0.f);
            __nv_bfloat162 a3 = __float2bfloat162_rn(0.f);
#pragma unroll
            for (int m = 0; m < 4; ++m) {
                a0 = __hfma2(u2bf2(carr[m].x), u2bf2(wq[m].x), a0);
                a1 = __hfma2(u2bf2(carr[m].y), u2bf2(wq[m].y), a1);
                a2 = __hfma2(u2bf2(carr[m].z), u2bf2(wq[m].z), a2);
                a3 = __hfma2(u2bf2(carr[m].w), u2bf2(wq[m].w), a3);
            }
            __nv_bfloat162 s01 = __hadd2(a0, a1);
            __nv_bfloat162 s23 = __hadd2(a2, a3);
            __nv_bfloat162 st  = __hadd2(s01, s23);
            float tot = __bfloat162float(__low2bfloat16(st)) +
                        __bfloat162float(__high2bfloat16(st));
            tot += __shfl_xor_sync(0xffffffffu, tot, 1);   // other i-half

            if (p == 0)
                s_c[buf ^ 1][j] =
                    __bfloat16_as_ushort(__float2bfloat16(tot * scale));
            __syncthreads();
        }
    }
#undef LOADW

    // Final contraction with right boundary + log-likelihood.
    float v = 0.f;
    if (tid < D_DIM)
        v = __bfloat162float(__ushort_as_bfloat16(s_c[0][tid])) * rb[tid];
#pragma unroll
    for (int o = 16; o >= 1; o >>= 1)
        v += __shfl_xor_sync(0xffffffffu, v, o);
    if (l == 0) s_red[w] = v;
    __syncthreads();
    if (tid == 0) {
        double ov = (double)s_red[0] + (double)s_red[1] +
                    (double)s_red[2] + (double)s_red[3];
        out[b] = (float)(2.0 * ((double)e_total * 0.6931471805599453 +
                                log(fabs(ov))));
    }
}

extern "C" void kernel_launch(void* const* d_in, const int* in_sizes, int n_in,
                              void* d_out, int out_size) {
    // metadata order: X [128*1024] i32, core [64*64*64] f32,
    //                 left_boundary [64] f32, right_boundary [64] f32
    const int*   X    = (const int*)  d_in[0];
    const float* core = (const float*)d_in[1];
    const float* lb   = (const float*)d_in[2];
    const float* rb   = (const float*)d_in[3];
    float*       out  = (float*)d_out;

    ttrain_pair_kernel<<<NPAIR, 128>>>(core);
    ttrain_main_kernel<<<128, 128>>>(X, lb, rb, out);
}

// round 9
// speedup vs baseline: 3.0050x; 1.1862x over previous
#include <cuda_runtime.h>
#include <cuda_bf16.h>
#include <math.h>

// Problem constants (fixed by the dataset): B=128, S=1024, d=64, D=64.
#define S_LEN   1024
#define NSTEP   512     // fused pair steps; DEPTH must divide NSTEP
#define D_DIM   64
#define NSYM    64
#define NPAIR   (NSYM * NSYM)
#define DEPTH   4       // ring depth; 512 % 4 == 0

// Pair table, bf16, stored in CONSUMPTION ORDER:
// tile(p) is 8KB; address (uint4 units) = p*512 + w*128 + m*32 + l, holding
// the m-th 16B (elements i = pp*32+8m .. +8) of the slice for consumer thread
// (w,l): j = 16w + (l>>1), pp = l&1, value = pairT[p][j][i] (i.e. the
// transposed pair product sum_j' core[s1][i][j'] * core[s2][j'][j]... k==j).
// Every consumer LDG.128 is a coalesced 512B warp transaction.
__device__ __nv_bfloat16 g_pairT[NPAIR * D_DIM * D_DIM];

__device__ __forceinline__ unsigned long long ffma2(unsigned long long a,
                                                    unsigned long long b,
                                                    unsigned long long c) {
    unsigned long long d;
    asm("fma.rn.f32x2 %0, %1, %2, %3;" : "=l"(d) : "l"(a), "l"(b), "l"(c));
    return d;
}
__device__ __forceinline__ unsigned long long packdup(float x) {
    unsigned long long d;
    asm("mov.b64 %0, {%1, %1};" : "=l"(d) : "f"(x));
    return d;
}
// pack two f32 into one bf16x2 u32: low 16 = lo (even index), high 16 = hi
__device__ __forceinline__ unsigned int bfpack(float lo, float hi) {
    unsigned int r;
    asm("cvt.rn.satfinite.bf16x2.f32 %0, %1, %2;" : "=r"(r) : "f"(hi), "f"(lo));
    return r;
}
// reinterpret a u32 as bf16x2 (via union; no pointer aliasing)
__device__ __forceinline__ __nv_bfloat162 u2bf2(unsigned int u) {
    union { unsigned int ui; __nv_bfloat162 b2; } cv;
    cv.ui = u;
    return cv.b2;
}

// ---------------------------------------------------------------------------
// Prep: build the 4096-pair table (8i x 4k register tiling, FMA-bound).
// One CTA (128 threads) per (s1,s2).  tid -> kb = tid&15 (k0=4*kb),
// ib = tid>>4 (i0=8*ib).  Output stored in the permuted consumption layout.
// ---------------------------------------------------------------------------
__global__ __launch_bounds__(128) void ttrain_pair_kernel(
    const float* __restrict__ core)
{
    const int p  = blockIdx.x;
    const int s1 = p >> 6;
    const int s2 = p & 63;

    __shared__ float AT[D_DIM * D_DIM];   // AT[j][i] = core[s1][i][j]
    __shared__ float Bs[D_DIM * D_DIM];   // Bs[j][k] = core[s2][j][k]

    const int tid = threadIdx.x;
    const float4* A4 = reinterpret_cast<const float4*>(core + (s1 << 12));
    const float4* B4 = reinterpret_cast<const float4*>(core + (s2 << 12));
    float4* Bs4 = reinterpret_cast<float4*>(Bs);

#pragma unroll
    for (int v = tid; v < 1024; v += 128) Bs4[v] = B4[v];
#pragma unroll
    for (int v = tid; v < 1024; v += 128) {
        float4 a = A4[v];
        int i = v >> 4;
        int jj = (v & 15) << 2;
        AT[ jj      * 64 + i] = a.x;
        AT[(jj + 1) * 64 + i] = a.y;
        AT[(jj + 2) * 64 + i] = a.z;
        AT[(jj + 3) * 64 + i] = a.w;
    }
    __syncthreads();

    const int kb = tid & 15;
    const int ib = tid >> 4;
    const int k0 = kb << 2;     // this thread: k0..k0+3
    const int i0 = ib << 3;     // this thread: i0..i0+7

    unsigned long long acc[4][4];   // [kk][i-pair], f32x2
#pragma unroll
    for (int a = 0; a < 4; ++a)
#pragma unroll
        for (int m = 0; m < 4; ++m) acc[a][m] = 0ull;

#pragma unroll 4
    for (int jj = 0; jj < 64; ++jj) {
        float4 b4 = *reinterpret_cast<const float4*>(Bs + jj * 64 + k0);
        unsigned long long bd0 = packdup(b4.x);
        unsigned long long bd1 = packdup(b4.y);
        unsigned long long bd2 = packdup(b4.z);
        unsigned long long bd3 = packdup(b4.w);
        const ulonglong2* av =
            reinterpret_cast<const ulonglong2*>(AT + jj * 64 + i0);
        ulonglong2 a01 = av[0], a23 = av[1];
        acc[0][0] = ffma2(a01.x, bd0, acc[0][0]);
        acc[0][1] = ffma2(a01.y, bd0, acc[0][1]);
        acc[0][2] = ffma2(a23.x, bd0, acc[0][2]);
        acc[0][3] = ffma2(a23.y, bd0, acc[0][3]);
        acc[1][0] = ffma2(a01.x, bd1, acc[1][0]);
        acc[1][1] = ffma2(a01.y, bd1, acc[1][1]);
        acc[1][2] = ffma2(a23.x, bd1, acc[1][2]);
        acc[1][3] = ffma2(a23.y, bd1, acc[1][3]);
        acc[2][0] = ffma2(a01.x, bd2, acc[2][0]);
        acc[2][1] = ffma2(a01.y, bd2, acc[2][1]);
        acc[2][2] = ffma2(a23.x, bd2, acc[2][2]);
        acc[2][3] = ffma2(a23.y, bd2, acc[2][3]);
        acc[3][0] = ffma2(a01.x, bd3, acc[3][0]);
        acc[3][1] = ffma2(a01.y, bd3, acc[3][1]);
        acc[3][2] = ffma2(a23.x, bd3, acc[3][2]);
        acc[3][3] = ffma2(a23.y, bd3, acc[3][3]);
    }

    // Store in consumption-order layout.  Each (kk) row's 8 bf16 (i0..i0+7)
    // is one 16B chunk: uint4 index = p*512 + (k>>4)*128 + m*32 + lane,
    // with m = ib&3 (since i0=8*ib, m=(i0&31)>>3) and
    // lane = (k&15)*2 + (i0>>5).
    uint4* out4 = reinterpret_cast<uint4*>(g_pairT);
    const int mchunk = ib & 3;
    const int ppbit  = ib >> 2;
#pragma unroll
    for (int kk = 0; kk < 4; ++kk) {
        const int k = k0 + kk;
        float2 f0 = *reinterpret_cast<float2*>(&acc[kk][0]);
        float2 f1 = *reinterpret_cast<float2*>(&acc[kk][1]);
        float2 f2 = *reinterpret_cast<float2*>(&acc[kk][2]);
        float2 f3 = *reinterpret_cast<float2*>(&acc[kk][3]);
        uint4 v = make_uint4(bfpack(f0.x, f0.y), bfpack(f1.x, f1.y),
                             bfpack(f2.x, f2.y), bfpack(f3.x, f3.y));
        out4[(p << 9) + ((k >> 4) << 7) + (mchunk << 5) +
             ((k & 15) << 1) + ppbit] = v;
    }
}

// ---------------------------------------------------------------------------
// Main chain, full-bf16 datapath.  One CTA (128 threads) per batch element,
// 512 fused steps.  warp w owns outputs j in [16w,16w+16); lane l:
// j = 16w + (l>>1), pp = l&1.  Thread does i in [32pp,32pp+32):
// 4 broadcast LDS.128 of bf16 c (FIRST, so the serial load sits at the front
// of the L1tex FIFO) + 4 coalesced LDG.128 prefetch (permuted layout: 4
// wavefronts each) + 16 HFMA2, pair-combined via one shfl, bf16 store.
// Renorm each step: exact power-of-two scale from exponent of c[0]
// (uniform; cancels exactly in the final log); zero exponent -> scale 1.
// ---------------------------------------------------------------------------
__global__ __launch_bounds__(128, 1) void ttrain_main_kernel(
    const int*   __restrict__ X,
    const float* __restrict__ lb,
    const float* __restrict__ rb,
    float*       __restrict__ out)
{
    __shared__ __align__(16) unsigned short s_c[2][D_DIM];  // bf16 c, dbl-buf
    __shared__ float s_red[4];
    __shared__ int   sP[NSTEP];

    const int tid = threadIdx.x;
    const int b   = blockIdx.x;
    const int w   = tid >> 5;
    const int l   = tid & 31;
    const int pp  = l & 1;

    // Stage fused pair indices: pidx[t] = X[2t]*64 + X[2t+1].
    const int2* Xb2 = reinterpret_cast<const int2*>(X + b * S_LEN);
    for (int k = tid; k < NSTEP; k += 128) {
        int2 x2 = Xb2[k];
        sP[k] = (x2.x << 6) | x2.y;
    }
    if (tid < D_DIM)
        s_c[0][tid] = __bfloat16_as_ushort(__float2bfloat16(lb[tid]));
    __syncthreads();

    // Permuted-layout slice: uint4 index within tile = w*128 + m*32 + l.
    const uint4* wbase = reinterpret_cast<const uint4*>(g_pairT);
    const int    toff  = (w << 7) + l;

    uint4 ring[DEPTH][4];
#define LOADW(dst, tt) {                                                   \
        const uint4* pw_ = wbase + (sP[(tt) & (NSTEP - 1)] << 9) + toff;   \
        (dst)[0] = pw_[0];  (dst)[1] = pw_[32];                            \
        (dst)[2] = pw_[64]; (dst)[3] = pw_[96]; }

    LOADW(ring[0], 0)
    LOADW(ring[1], 1)
    LOADW(ring[2], 2)

    int e_total = 0;

    for (int t0 = 0; t0 < NSTEP; t0 += DEPTH) {    // NSTEP % DEPTH == 0
#pragma unroll
        for (int u = 0; u < DEPTH; ++u) {
            const int t   = t0 + u;
            const int buf = t & 1;

            // --- serial-dependency loads FIRST (front of L1tex FIFO) ---
            unsigned short c0b = s_c[buf][0];
            const uint4* cv4 =
                reinterpret_cast<const uint4*>(&s_c[buf][pp << 5]);
            uint4 carr[4];
#pragma unroll
            for (int m = 0; m < 4; ++m) carr[m] = cv4[m];

            // --- prefetch (off the critical path) ---
            LOADW(ring[(u + DEPTH - 1) % DEPTH], t + DEPTH - 1)

            // Renorm scale from c[0]'s exponent (bf16 = fp32 exponent field).
            int ef = (c0b >> 7) & 0xff;
            int e  = (ef == 0) ? 0 : ef - 127;
            e = e < -96 ? -96 : (e > 96 ? 96 : e);
            e_total += e;
            const float scale = __int_as_float((127 - e) << 23);

            const uint4* wq = ring[u];

            __nv_bfloat162 a0 = __float2bfloat162_rn(0.f);
            __nv_bfloat162 a1 = __float2bfloat162_rn(0.f);
            __nv_bfloat162 a2 = __float2bfloat162_rn(0.f);
            __nv_bfloat162 a3 = __float2bfloat162_rn(0.f);
#pragma unroll
            for (int m = 0; m < 4; ++m) {
                a0 = __hfma2(u2bf2(carr[m].x), u2bf2(wq[m].x), a0);
                a1 = __hfma2(u2bf2(carr[m].y), u2bf2(wq[m].y), a1);
                a2 = __hfma2(u2bf2(carr[m].z), u2bf2(wq[m].z), a2);
                a3 = __hfma2(u2bf2(carr[m].w), u2bf2(wq[m].w), a3);
            }
            __nv_bfloat162 s01 = __hadd2(a0, a1);
            __nv_bfloat162 s23 = __hadd2(a2, a3);
            __nv_bfloat162 st  = __hadd2(s01, s23);
            float tot = __bfloat162float(__low2bfloat16(st)) +
                        __bfloat162float(__high2bfloat16(st));
            tot += __shfl_xor_sync(0xffffffffu, tot, 1);   // other i-half

            if (pp == 0)
                s_c[buf ^ 1][(w << 4) + (l >> 1)] =
                    __bfloat16_as_ushort(__float2bfloat16(tot * scale));
            __syncthreads();
        }
    }
#undef LOADW

    // Final contraction with right boundary + log-likelihood.
    float v = 0.f;
    if (tid < D_DIM)
        v = __bfloat162float(__ushort_as_bfloat16(s_c[0][tid])) * rb[tid];
#pragma unroll
    for (int o = 16; o >= 1; o >>= 1)
        v += __shfl_xor_sync(0xffffffffu, v, o);
    if (l == 0) s_red[w] = v;
    __syncthreads();
    if (tid == 0) {
        double ov = (double)s_red[0] + (double)s_red[1] +
                    (double)s_red[2] + (double)s_red[3];
        out[b] = (float)(2.0 * ((double)e_total * 0.6931471805599453 +
                                log(fabs(ov))));
    }
}

extern "C" void kernel_launch(void* const* d_in, const int* in_sizes, int n_in,
                              void* d_out, int out_size) {
    // metadata order: X [128*1024] i32, core [64*64*64] f32,
    //                 left_boundary [64] f32, right_boundary [64] f32
    const int*   X    = (const int*)  d_in[0];
    const float* core = (const float*)d_in[1];
    const float* lb   = (const float*)d_in[2];
    const float* rb   = (const float*)d_in[3];
    float*       out  = (float*)d_out;

    ttrain_pair_kernel<<<NPAIR, 128>>>(core);
    ttrain_main_kernel<<<128, 128>>>(X, lb, rb, out);
}